// round 16
// baseline (speedup 1.0000x reference)
#include <cuda_runtime.h>
#include <cuda_fp16.h>
#include <cstdint>

// Problem constants
#define B_  2
#define S_  2048
#define D_  1024
#define H_  16
#define HD_ 64
#define N3_ 3072
#define M_  (B_ * S_)   // 4096

// fp16 hi/lo pairs: split inputs for projection GEMM, and split KQV output.
__device__ __half g_Ah[(size_t)M_ * D_];
__device__ __half g_Al[(size_t)M_ * D_];
__device__ __half g_Wh[(size_t)N3_ * D_];   // W transposed: [n][k]
__device__ __half g_Wl[(size_t)N3_ * D_];
__device__ __half g_kqvh[(size_t)M_ * N3_]; // [token][3072]: K|Q|V
__device__ __half g_kqvl[(size_t)M_ * N3_]; // lo residual (V columns never read)

typedef unsigned long long ull;

// ===================== helpers =====================
__device__ __forceinline__ uint32_t smem_u32(const void* p) {
    uint32_t a;
    asm("{ .reg .u64 t; cvta.to.shared.u64 t, %1; cvt.u32.u64 %0, t; }" : "=r"(a) : "l"(p));
    return a;
}
#define SWZ(o) ((o) ^ (((o) >> 3) & 0x70))
// 64-byte-row tiles: addr = row*64 + (cb ^ ((row&6)<<3)); conflict-free for
// ldsm (8 rows spread over {0,16,...,112} mod 128) and 16B cp.async stores.
#define SWZ64R(row, cb) ((uint32_t)(row) * 64u + ((uint32_t)(cb) ^ (((uint32_t)(row) & 6u) << 3)))

__device__ __forceinline__ void cp_async16(uint32_t dst, const void* src) {
    asm volatile("cp.async.cg.shared.global [%0], [%1], 16;" :: "r"(dst), "l"(src));
}
__device__ __forceinline__ void cp_async4(uint32_t dst, const void* src) {
    asm volatile("cp.async.ca.shared.global [%0], [%1], 4;" :: "r"(dst), "l"(src));
}
__device__ __forceinline__ void cp_commit() { asm volatile("cp.async.commit_group;" ::: "memory"); }
__device__ __forceinline__ void cp_wait0()  { asm volatile("cp.async.wait_group 0;" ::: "memory"); }

__device__ __forceinline__ void ldsm_x4(uint32_t* r, uint32_t addr) {
    asm volatile("ldmatrix.sync.aligned.m8n8.x4.shared.b16 {%0,%1,%2,%3}, [%4];"
        : "=r"(r[0]), "=r"(r[1]), "=r"(r[2]), "=r"(r[3]) : "r"(addr));
}
__device__ __forceinline__ void ldsm_x4_t(uint32_t* r, uint32_t addr) {
    asm volatile("ldmatrix.sync.aligned.m8n8.x4.trans.shared.b16 {%0,%1,%2,%3}, [%4];"
        : "=r"(r[0]), "=r"(r[1]), "=r"(r[2]), "=r"(r[3]) : "r"(addr));
}
__device__ __forceinline__ void mma_f16(float* d, const uint32_t* a, const uint32_t* b) {
    asm volatile("mma.sync.aligned.m16n8k16.row.col.f32.f16.f16.f32 "
        "{%0,%1,%2,%3}, {%4,%5,%6,%7}, {%8,%9}, {%0,%1,%2,%3};"
        : "+f"(d[0]), "+f"(d[1]), "+f"(d[2]), "+f"(d[3])
        : "r"(a[0]), "r"(a[1]), "r"(a[2]), "r"(a[3]), "r"(b[0]), "r"(b[1]));
}

// pack two fp32 into one f16x2 (a -> low half, b -> high half)
__device__ __forceinline__ uint32_t cvt_f16x2(float a, float b) {
    uint32_t r;
    asm("cvt.rn.f16x2.f32 %0, %1, %2;" : "=r"(r) : "f"(b), "f"(a));
    return r;
}

// hi/lo split: 1 packed cvt for hi, widen back, subtract, 1 packed cvt for lo.
__device__ __forceinline__ void split2(float a, float b, uint32_t& h2, uint32_t& l2) {
    h2 = cvt_f16x2(a, b);
    __half2 hh = *(__half2*)&h2;
    float2 hf = __half22float2(hh);
    l2 = cvt_f16x2(a - hf.x, b - hf.y);
}

// p = exp(clip(elu(u), -10, 10)) with ONE MUFU exp:
//   u > 0 : exp(min(u,10)) = min(exp(u), e^10)        (monotonicity)
//   u <= 0: exp(t-1), t = exp(u) in (0,1] — degree-5 Taylor at z=t-0.5,
//           |z|<=0.5 -> rel err <= ~6e-5, FMAs on the fma pipe.
__device__ __forceinline__ float elu_exp(float u) {
    float t = __expf(u);
    float z = t - 0.5f;
    float p = 0.008333334f;               // 1/120
    p = fmaf(p, z, 0.041666668f);         // 1/24
    p = fmaf(p, z, 0.16666667f);          // 1/6
    p = fmaf(p, z, 0.5f);
    p = fmaf(p, z, 1.0f);
    p = fmaf(p, z, 1.0f);
    p *= 0.60653066f;                     // e^-0.5
    return u > 0.f ? fminf(t, 22026.466f) : p;
}

// ============================================================================
// Split kernels: fp32 -> (hi, lo) fp16 pair
// ============================================================================
__global__ void split_a_kernel(const float* __restrict__ in) {
    size_t i = ((size_t)blockIdx.x * 256 + threadIdx.x) * 4;
    float4 v = *(const float4*)(in + i);
    float x[4] = {v.x, v.y, v.z, v.w};
    #pragma unroll
    for (int j = 0; j < 4; ++j) {
        __half h = __float2half_rn(x[j]);
        g_Ah[i + j] = h;
        g_Al[i + j] = __float2half_rn(x[j] - __half2float(h));
    }
}

__global__ void split_w_kernel(const float* __restrict__ W) {
    __shared__ float t[32][33];
    int tx = threadIdx.x, ty = threadIdx.y;
    int n0 = blockIdx.x * 32, k0 = blockIdx.y * 32;
    #pragma unroll
    for (int i = 0; i < 4; ++i)
        t[ty + i * 8][tx] = W[(size_t)(k0 + ty + i * 8) * N3_ + n0 + tx];
    __syncthreads();
    #pragma unroll
    for (int i = 0; i < 4; ++i) {
        float x = t[tx][ty + i * 8];
        size_t o = (size_t)(n0 + ty + i * 8) * D_ + k0 + tx;
        __half h = __float2half_rn(x);
        g_Wh[o] = h;
        g_Wl[o] = __float2half_rn(x - __half2float(h));
    }
}

// ============================================================================
// HMMA projection GEMM: kqv = A @ W + bias, output written as fp16 hi/lo.
// CTA 128x128, K-chunk 32, DOUBLE-buffered 32KB stages (64KB total, 2 CTAs/SM).
// Loads of chunk kt+1 are issued before compute(kt) -> fully overlapped.
// K,Q columns (n0 < 2048): 3 products (hi*hi + hi*lo + lo*hi) — score path.
// V columns (n0 >= 2048): SINGLE product (V is fp16-truncated in PV anyway).
// ============================================================================
#define GM 128
#define GN 128
#define GKC 32
#define NCHUNK (D_ / GKC)          // 32
#define OPBYTES (GM * GKC * 2)     // 8192 per operand tile (64B rows)
#define STAGE_BYTES (4 * OPBYTES)  // 32768
#define GEMM_SMEM (2 * STAGE_BYTES) // 65536

__global__ __launch_bounds__(256, 2) void gemm_mma_kernel(const float* __restrict__ bias)
{
    extern __shared__ char smem[];
    const uint32_t sb = smem_u32(smem);
    const int tid = threadIdx.x, lane = tid & 31, wid = tid >> 5;
    const int wm = wid & 1, wn = wid >> 1;
    const int m0 = blockIdx.y * GM, n0 = blockIdx.x * GN;
    const bool is_v = (n0 >= 2 * D_);   // V columns: single-product path

    auto load_chunk = [&](int c, int st) {
        const size_t kb = (size_t)c * GKC;
        const uint32_t base = sb + st * STAGE_BYTES;
        #pragma unroll
        for (int i = 0; i < 2; ++i) {
            int idx = tid + i * 256;
            int r = idx >> 2, ch = idx & 3;          // 128 rows x 4 chunks of 16B
            uint32_t off = SWZ64R(r, ch * 16);
            const size_t ga = (size_t)(m0 + r) * D_ + kb + ch * 8;
            const size_t gb = (size_t)(n0 + r) * D_ + kb + ch * 8;
            cp_async16(base + off,               g_Ah + ga);
            cp_async16(base + 2 * OPBYTES + off, g_Wh + gb);
            if (!is_v) {
                cp_async16(base + OPBYTES + off,     g_Al + ga);
                cp_async16(base + 3 * OPBYTES + off, g_Wl + gb);
            }
        }
    };

    float acc[4][4][4];
    #pragma unroll
    for (int mt = 0; mt < 4; ++mt)
        #pragma unroll
        for (int nt = 0; nt < 4; ++nt)
            #pragma unroll
            for (int r = 0; r < 4; ++r) acc[mt][nt][r] = 0.f;

    const int a_row = wm * 64 + (lane & 15);          // + mt*16
    const int a_kb  = (lane >> 4) * 16;               // + ks*32
    const int b_row = wn * 32 + ((lane >> 4) & 1) * 8 + (lane & 7);  // + nt2*16
    const int b_kb  = ((lane >> 3) & 1) * 16;         // + ks*32

    load_chunk(0, 0);
    cp_commit();

    for (int kt = 0; kt < NCHUNK; ++kt) {
        const int st = kt & 1;
        cp_wait0();            // chunk kt arrived in buffer st
        __syncthreads();       // all warps done with buffer st^1 (chunk kt-1)
        if (kt + 1 < NCHUNK) { load_chunk(kt + 1, st ^ 1); cp_commit(); }

        const uint32_t base = sb + st * STAGE_BYTES;
        if (!is_v) {
            #pragma unroll
            for (int ks = 0; ks < 2; ++ks) {
                uint32_t bh[2][4], bl[2][4];
                #pragma unroll
                for (int nt2 = 0; nt2 < 2; ++nt2) {
                    uint32_t off = SWZ64R(b_row + nt2 * 16, ks * 32 + b_kb);
                    ldsm_x4(bh[nt2], base + 2 * OPBYTES + off);
                    ldsm_x4(bl[nt2], base + 3 * OPBYTES + off);
                }
                #pragma unroll
                for (int mt = 0; mt < 4; ++mt) {
                    uint32_t ah[4], al[4];
                    uint32_t off = SWZ64R(a_row + mt * 16, ks * 32 + a_kb);
                    ldsm_x4(ah, base + off);
                    ldsm_x4(al, base + OPBYTES + off);
                    #pragma unroll
                    for (int nt = 0; nt < 4; ++nt) {
                        const uint32_t* ph = &bh[nt >> 1][(nt & 1) * 2];
                        const uint32_t* pl = &bl[nt >> 1][(nt & 1) * 2];
                        mma_f16(acc[mt][nt], ah, ph);
                        mma_f16(acc[mt][nt], ah, pl);
                        mma_f16(acc[mt][nt], al, ph);
                    }
                }
            }
        } else {
            #pragma unroll
            for (int ks = 0; ks < 2; ++ks) {
                uint32_t bh[2][4];
                #pragma unroll
                for (int nt2 = 0; nt2 < 2; ++nt2) {
                    uint32_t off = SWZ64R(b_row + nt2 * 16, ks * 32 + b_kb);
                    ldsm_x4(bh[nt2], base + 2 * OPBYTES + off);
                }
                #pragma unroll
                for (int mt = 0; mt < 4; ++mt) {
                    uint32_t ah[4];
                    uint32_t off = SWZ64R(a_row + mt * 16, ks * 32 + a_kb);
                    ldsm_x4(ah, base + off);
                    #pragma unroll
                    for (int nt = 0; nt < 4; ++nt)
                        mma_f16(acc[mt][nt], ah, &bh[nt >> 1][(nt & 1) * 2]);
                }
            }
        }
    }

    // Epilogue: bias add; K,Q: split to fp16 hi/lo; V: hi only (lo never read).
    const int grp = lane >> 2, qc = (lane & 3) * 2;
    #pragma unroll
    for (int mt = 0; mt < 4; ++mt) {
        const int r0 = m0 + wm * 64 + mt * 16 + grp;
        #pragma unroll
        for (int nt = 0; nt < 4; ++nt) {
            const int col = n0 + wn * 32 + nt * 8 + qc;
            const float2 bv = *(const float2*)(bias + col);
            float o0 = acc[mt][nt][0] + bv.x, o1 = acc[mt][nt][1] + bv.y;
            float o2 = acc[mt][nt][2] + bv.x, o3 = acc[mt][nt][3] + bv.y;
            size_t off0 = (size_t)r0 * N3_ + col;
            size_t off1 = off0 + 8 * (size_t)N3_;
            if (!is_v) {
                uint32_t h2, l2;
                split2(o0, o1, h2, l2);
                *(uint32_t*)(g_kqvh + off0) = h2;
                *(uint32_t*)(g_kqvl + off0) = l2;
                split2(o2, o3, h2, l2);
                *(uint32_t*)(g_kqvh + off1) = h2;
                *(uint32_t*)(g_kqvl + off1) = l2;
            } else {
                *(uint32_t*)(g_kqvh + off0) = cvt_f16x2(o0, o1);
                *(uint32_t*)(g_kqvh + off1) = cvt_f16x2(o2, o3);
            }
        }
    }
}

// ============================================================================
// Tensor-core flash attention — fused per-key-group pipeline (R14/R15 best).
// Per key tile (64 keys), loop over 4 key-groups of 16:
//   score(24 mma) -> epilogue(8 exp, in regs) -> PV(8 mma)
// Score: 3 fp16 hi/lo products. PV: single product P_f16 x V_f16.
// K/V double-buffered: ONE __syncthreads + ONE cp.wait per key tile.
// ============================================================================
#define BQ 128
#define BK 64
#define NKT (S_ / BK)     // 32

// smem byte offsets (80.5 KB total -> 2 CTAs/SM)
#define QH_OFF 0
#define QL_OFF 16384
#define KH_OFF 32768      // + st*8192
#define KL_OFF 49152      // + st*8192
#define VH_OFF 65536      // + st*8192
#define MK_OFF 81920      // + st*256
#define ATTN_SMEM 82432

__global__ __launch_bounds__(256, 2) void attn_mma_kernel(
    const float* __restrict__ masks, float* __restrict__ out)
{
    extern __shared__ char smem[];
    const uint32_t sb = smem_u32(smem);
    const int tid = threadIdx.x, lane = tid & 31, wid = tid >> 5;
    const int b = blockIdx.z, h = blockIdx.y;
    const int q0 = blockIdx.x * BQ;
    const int grp = lane >> 2, qc = (lane & 3) * 2;

    // fragment address pieces
    const int a_row = wid * 16 + (lane & 15);                 // Q rows for this warp
    const int a_kb  = (lane >> 4) * 16;
    const int bk_sub = ((lane >> 4) & 1) * 8 + (lane & 7);    // + nt2*16 (key rows)
    const int bk_kb  = ((lane >> 3) & 1) * 16;
    const int v_row  = ((lane >> 3) & 1) * 8 + (lane & 7);    // + nt2*16
    const int v_cb   = ((lane >> 4) & 1) * 16;                // + vb*32 (d bytes)

    auto load_kv = [&](int kt2, int st2) {
        const size_t tok0 = (size_t)(b * S_) + kt2 * BK;
        #pragma unroll
        for (int i = 0; i < 2; ++i) {
            int idx = tid + i * 256;
            int r = idx >> 3, ch = idx & 7;
            uint32_t off = SWZ((uint32_t)(r * 128 + ch * 16)) + st2 * 8192;
            size_t g = (tok0 + r) * N3_ + h * HD_ + ch * 8;
            cp_async16(sb + KH_OFF + off, g_kqvh + g);
            cp_async16(sb + KL_OFF + off, g_kqvl + g);
            cp_async16(sb + VH_OFF + off, g_kqvh + g + 2 * D_);
        }
        if (tid < BK)
            cp_async4(sb + MK_OFF + (kt2 & 1) * 256 + tid * 4,
                      masks + (size_t)b * S_ + kt2 * BK + tid);
    };

    // Prologue: Q tile + K/V(0) + mask(0), one commit group.
    #pragma unroll
    for (int i = 0; i < 4; ++i) {
        int idx = tid + i * 256;
        int r = idx >> 3, ch = idx & 7;
        uint32_t off = SWZ((uint32_t)(r * 128 + ch * 16));
        size_t g = (size_t)(b * S_ + q0 + r) * N3_ + D_ + h * HD_ + ch * 8;
        cp_async16(sb + QH_OFF + off, g_kqvh + g);
        cp_async16(sb + QL_OFF + off, g_kqvl + g);
    }
    load_kv(0, 0);
    cp_commit();
    cp_wait0();
    __syncthreads();

    // Q fragments -> registers, once (loop-invariant across all key tiles).
    uint32_t aqh[4][4], aql[4][4];
    #pragma unroll
    for (int ks = 0; ks < 4; ++ks) {
        uint32_t off = SWZ((uint32_t)(a_row * 128 + ks * 32 + a_kb));
        ldsm_x4(aqh[ks], sb + QH_OFF + off);
        ldsm_x4(aql[ks], sb + QL_OFF + off);
    }

    float acc_o[8][4];
    #pragma unroll
    for (int nt = 0; nt < 8; ++nt)
        #pragma unroll
        for (int r = 0; r < 4; ++r) acc_o[nt][r] = 0.f;
    float den0 = 0.f, den1 = 0.f;

    for (int kt = 0; kt < NKT; ++kt) {
        const int st = kt & 1;
        if (kt > 0) {
            // K/V/mask(kt) arrived; all warps done reading buffer st^1.
            cp_wait0();
            __syncthreads();
        }
        // Prefetch next tile into the other buffer (overlaps this tile's math).
        if (kt + 1 < NKT) { load_kv(kt + 1, st ^ 1); cp_commit(); }

        const float* mk = (const float*)(smem + MK_OFF + st * 256);

        // ---- fused per-key-group pipeline: score -> epilogue -> PV ----
        #pragma unroll
        for (int nt2 = 0; nt2 < 4; ++nt2) {
            // score: S[16 q][16 k(nt2)] over d=64 (3 products)
            float acc_s[2][4];
            #pragma unroll
            for (int hf = 0; hf < 2; ++hf)
                #pragma unroll
                for (int r = 0; r < 4; ++r) acc_s[hf][r] = 0.f;

            #pragma unroll
            for (int ks = 0; ks < 4; ++ks) {
                uint32_t bkh[4], bkl[4];
                uint32_t off = SWZ((uint32_t)((nt2 * 16 + bk_sub) * 128 + ks * 32 + bk_kb))
                               + st * 8192;
                ldsm_x4(bkh, sb + KH_OFF + off);
                ldsm_x4(bkl, sb + KL_OFF + off);
                #pragma unroll
                for (int hf = 0; hf < 2; ++hf) {
                    float* d = acc_s[hf];
                    mma_f16(d, aqh[ks], &bkh[hf * 2]);
                    mma_f16(d, aqh[ks], &bkl[hf * 2]);
                    mma_f16(d, aql[ks], &bkh[hf * 2]);
                }
            }

            // epilogue: p = exp(clip(elu(s)))*mask_k ; pack as PV A-fragment
            uint32_t pf[4];
            #pragma unroll
            for (int hf = 0; hf < 2; ++hf) {
                const int c = nt2 * 16 + hf * 8 + qc;
                float m0 = mk[c], m1 = mk[c + 1];
                float p0 = elu_exp(acc_s[hf][0]) * m0;
                float p1 = elu_exp(acc_s[hf][1]) * m1;
                float p2 = elu_exp(acc_s[hf][2]) * m0;
                float p3 = elu_exp(acc_s[hf][3]) * m1;
                den0 += p0 + p1;
                den1 += p2 + p3;
                pf[hf * 2 + 0] = cvt_f16x2(p0, p1);
                pf[hf * 2 + 1] = cvt_f16x2(p2, p3);
            }

            // PV: O[16 q][64 d] += P[16][16(nt2)] @ V[16(nt2)][64]
            #pragma unroll
            for (int vb = 0; vb < 4; ++vb) {
                uint32_t bvh[4];
                uint32_t off = SWZ((uint32_t)((nt2 * 16 + v_row) * 128 + vb * 32 + v_cb))
                               + st * 8192;
                ldsm_x4_t(bvh, sb + VH_OFF + off);
                mma_f16(acc_o[vb * 2 + 0], pf, &bvh[0]);
                mma_f16(acc_o[vb * 2 + 1], pf, &bvh[2]);
            }
        }
        // Next iteration's cp_wait0+sync protects buffer st^1 before overwrite of st.
    }

    // ---- denominator reduce (within warp: lane bits 0,1) + writeback ----
    den0 += __shfl_xor_sync(0xffffffffu, den0, 1);
    den0 += __shfl_xor_sync(0xffffffffu, den0, 2);
    den1 += __shfl_xor_sync(0xffffffffu, den1, 1);
    den1 += __shfl_xor_sync(0xffffffffu, den1, 2);

    const int r0 = wid * 16 + grp;
    const int r1 = r0 + 8;
    float s0 = masks[(size_t)b * S_ + q0 + r0] / den0;
    float s1 = masks[(size_t)b * S_ + q0 + r1] / den1;
    #pragma unroll
    for (int nt = 0; nt < 8; ++nt) {
        const int c = nt * 8 + qc;
        float* p0 = out + (size_t)(b * S_ + q0 + r0) * D_ + h * HD_ + c;
        float* p1 = out + (size_t)(b * S_ + q0 + r1) * D_ + h * HD_ + c;
        *(float2*)p0 = make_float2(acc_o[nt][0] * s0, acc_o[nt][1] * s0);
        *(float2*)p1 = make_float2(acc_o[nt][2] * s1, acc_o[nt][3] * s1);
    }
}

// ============================================================================
// Launch
// ============================================================================
extern "C" void kernel_launch(void* const* d_in, const int* in_sizes, int n_in,
                              void* d_out, int out_size)
{
    const float *inp = nullptr, *msk = nullptr, *W = nullptr, *bias = nullptr;
    for (int i = 0; i < n_in; ++i) {
        switch (in_sizes[i]) {
            case M_ * D_:   inp  = (const float*)d_in[i]; break;  // inputs  [2,2048,1024]
            case B_ * S_:   msk  = (const float*)d_in[i]; break;  // masks   [2,2048]
            case D_ * N3_:  W    = (const float*)d_in[i]; break;  // W       [1024,3072]
            case N3_:       bias = (const float*)d_in[i]; break;  // b       [3072]
        }
    }

    cudaFuncSetAttribute(gemm_mma_kernel,
                         cudaFuncAttributeMaxDynamicSharedMemorySize, GEMM_SMEM);
    cudaFuncSetAttribute(attn_mma_kernel,
                         cudaFuncAttributeMaxDynamicSharedMemorySize, ATTN_SMEM);

    split_a_kernel<<<(M_ * D_) / 1024, 256>>>(inp);
    split_w_kernel<<<dim3(N3_ / 32, D_ / 32), dim3(32, 8)>>>(W);

    dim3 g1(N3_ / GN, M_ / GM);            // (24, 32)
    gemm_mma_kernel<<<g1, 256, GEMM_SMEM>>>(bias);

    dim3 g2(S_ / BQ, H_, B_);              // (16, 16, 2)
    attn_mma_kernel<<<g2, 256, ATTN_SMEM>>>(msk, (float*)d_out);
}

// round 17
// speedup vs baseline: 1.0149x; 1.0149x over previous
#include <cuda_runtime.h>
#include <cuda_fp16.h>
#include <cstdint>

// Problem constants
#define B_  2
#define S_  2048
#define D_  1024
#define H_  16
#define HD_ 64
#define N3_ 3072
#define M_  (B_ * S_)   // 4096

// fp16 hi/lo pairs: split inputs for projection GEMM, and split KQV output.
__device__ __half g_Ah[(size_t)M_ * D_];
__device__ __half g_Al[(size_t)M_ * D_];
__device__ __half g_Wh[(size_t)N3_ * D_];   // W transposed: [n][k]
__device__ __half g_Wl[(size_t)N3_ * D_];
__device__ __half g_kqvh[(size_t)M_ * N3_]; // [token][3072]: K|Q|V
__device__ __half g_kqvl[(size_t)M_ * N3_]; // lo residual (V columns never read)

typedef unsigned long long ull;

// ===================== helpers =====================
__device__ __forceinline__ uint32_t smem_u32(const void* p) {
    uint32_t a;
    asm("{ .reg .u64 t; cvta.to.shared.u64 t, %1; cvt.u32.u64 %0, t; }" : "=r"(a) : "l"(p));
    return a;
}
#define SWZ(o) ((o) ^ (((o) >> 3) & 0x70))

__device__ __forceinline__ void cp_async16(uint32_t dst, const void* src) {
    asm volatile("cp.async.cg.shared.global [%0], [%1], 16;" :: "r"(dst), "l"(src));
}
__device__ __forceinline__ void cp_async4(uint32_t dst, const void* src) {
    asm volatile("cp.async.ca.shared.global [%0], [%1], 4;" :: "r"(dst), "l"(src));
}
__device__ __forceinline__ void cp_commit() { asm volatile("cp.async.commit_group;" ::: "memory"); }
__device__ __forceinline__ void cp_wait0()  { asm volatile("cp.async.wait_group 0;" ::: "memory"); }

__device__ __forceinline__ void ldsm_x4(uint32_t* r, uint32_t addr) {
    asm volatile("ldmatrix.sync.aligned.m8n8.x4.shared.b16 {%0,%1,%2,%3}, [%4];"
        : "=r"(r[0]), "=r"(r[1]), "=r"(r[2]), "=r"(r[3]) : "r"(addr));
}
__device__ __forceinline__ void ldsm_x4_t(uint32_t* r, uint32_t addr) {
    asm volatile("ldmatrix.sync.aligned.m8n8.x4.trans.shared.b16 {%0,%1,%2,%3}, [%4];"
        : "=r"(r[0]), "=r"(r[1]), "=r"(r[2]), "=r"(r[3]) : "r"(addr));
}
__device__ __forceinline__ void mma_f16(float* d, const uint32_t* a, const uint32_t* b) {
    asm volatile("mma.sync.aligned.m16n8k16.row.col.f32.f16.f16.f32 "
        "{%0,%1,%2,%3}, {%4,%5,%6,%7}, {%8,%9}, {%0,%1,%2,%3};"
        : "+f"(d[0]), "+f"(d[1]), "+f"(d[2]), "+f"(d[3])
        : "r"(a[0]), "r"(a[1]), "r"(a[2]), "r"(a[3]), "r"(b[0]), "r"(b[1]));
}

// pack two fp32 into one f16x2 (a -> low half, b -> high half)
__device__ __forceinline__ uint32_t cvt_f16x2(float a, float b) {
    uint32_t r;
    asm("cvt.rn.f16x2.f32 %0, %1, %2;" : "=r"(r) : "f"(b), "f"(a));
    return r;
}

// hi/lo split: 1 packed cvt for hi, widen back, subtract, 1 packed cvt for lo.
__device__ __forceinline__ void split2(float a, float b, uint32_t& h2, uint32_t& l2) {
    h2 = cvt_f16x2(a, b);
    __half2 hh = *(__half2*)&h2;
    float2 hf = __half22float2(hh);
    l2 = cvt_f16x2(a - hf.x, b - hf.y);
}

// p = exp(clip(elu(u), -10, 10)) with ONE MUFU exp:
//   u > 0 : exp(min(u,10)) = min(exp(u), e^10)        (monotonicity)
//   u <= 0: exp(t-1), t = exp(u) in (0,1] — degree-5 Taylor at z=t-0.5,
//           |z|<=0.5 -> rel err <= ~6e-5, FMAs on the fma pipe.
__device__ __forceinline__ float elu_exp(float u) {
    float t = __expf(u);
    float z = t - 0.5f;
    float p = 0.008333334f;               // 1/120
    p = fmaf(p, z, 0.041666668f);         // 1/24
    p = fmaf(p, z, 0.16666667f);          // 1/6
    p = fmaf(p, z, 0.5f);
    p = fmaf(p, z, 1.0f);
    p = fmaf(p, z, 1.0f);
    p *= 0.60653066f;                     // e^-0.5
    return u > 0.f ? fminf(t, 22026.466f) : p;
}

// ============================================================================
// Fused split kernel: fp32 -> (hi, lo) fp16 pair for both A and W (transposed).
// Blocks [0, 4096): A elementwise split. Blocks [4096, 7168): W 32x32
// transpose tiles. One launch; the two memory-bound phases co-run.
// ============================================================================
#define SPLIT_A_BLOCKS (M_ * D_ / 1024)          // 4096
#define SPLIT_W_BLOCKS ((N3_ / 32) * (D_ / 32))  // 3072
__global__ void split_fused_kernel(const float* __restrict__ in,
                                   const float* __restrict__ W) {
    __shared__ float t[32][33];
    const int tid = threadIdx.x;
    if (blockIdx.x < SPLIT_A_BLOCKS) {
        size_t i = ((size_t)blockIdx.x * 256 + tid) * 4;
        float4 v = *(const float4*)(in + i);
        float x[4] = {v.x, v.y, v.z, v.w};
        #pragma unroll
        for (int j = 0; j < 4; ++j) {
            __half h = __float2half_rn(x[j]);
            g_Ah[i + j] = h;
            g_Al[i + j] = __float2half_rn(x[j] - __half2float(h));
        }
    } else {
        const int wb = blockIdx.x - SPLIT_A_BLOCKS;
        const int n0 = (wb % (N3_ / 32)) * 32, k0 = (wb / (N3_ / 32)) * 32;
        const int tx = tid & 31, ty = tid >> 5;
        #pragma unroll
        for (int i = 0; i < 4; ++i)
            t[ty + i * 8][tx] = W[(size_t)(k0 + ty + i * 8) * N3_ + n0 + tx];
        __syncthreads();
        #pragma unroll
        for (int i = 0; i < 4; ++i) {
            float x = t[tx][ty + i * 8];
            size_t o = (size_t)(n0 + ty + i * 8) * D_ + k0 + tx;
            __half h = __float2half_rn(x);
            g_Wh[o] = h;
            g_Wl[o] = __float2half_rn(x - __half2float(h));
        }
    }
}

// ============================================================================
// HMMA projection GEMM (R15 config — proven best): kqv = A @ W + bias,
// output fp16 hi/lo. CTA 128x128, K-chunk 64, single-buffered 64KB stage,
// 2 CTAs/SM (co-resident CTA covers load latency; R16 disproved the
// double-buffer hypothesis).
// K,Q columns (n0 < 2048): 3 products. V columns (n0 >= 2048): 1 product.
// ============================================================================
#define GM 128
#define GN 128
#define GKC 64
#define NCHUNK (D_ / GKC)          // 16
#define OPBYTES (GM * GKC * 2)     // 16384 per operand tile
#define STAGE_BYTES (4 * OPBYTES)  // 65536
#define GEMM_SMEM STAGE_BYTES

__global__ __launch_bounds__(256, 2) void gemm_mma_kernel(const float* __restrict__ bias)
{
    extern __shared__ char smem[];
    const uint32_t sb = smem_u32(smem);
    const int tid = threadIdx.x, lane = tid & 31, wid = tid >> 5;
    const int wm = wid & 1, wn = wid >> 1;
    const int m0 = blockIdx.y * GM, n0 = blockIdx.x * GN;
    const bool is_v = (n0 >= 2 * D_);   // V columns: single-product path

    auto load_chunk = [&](int c) {
        const size_t kb = (size_t)c * GKC;
        #pragma unroll
        for (int i = 0; i < 4; ++i) {
            int idx = tid + i * 256;
            int r = idx >> 3, ch = idx & 7;
            uint32_t off = SWZ((uint32_t)(r * 128 + ch * 16));
            const size_t ga = (size_t)(m0 + r) * D_ + kb + ch * 8;
            const size_t gb = (size_t)(n0 + r) * D_ + kb + ch * 8;
            cp_async16(sb + off,               g_Ah + ga);
            cp_async16(sb + 2 * OPBYTES + off, g_Wh + gb);
            if (!is_v) {
                cp_async16(sb + OPBYTES + off,     g_Al + ga);
                cp_async16(sb + 3 * OPBYTES + off, g_Wl + gb);
            }
        }
    };

    float acc[4][4][4];
    #pragma unroll
    for (int mt = 0; mt < 4; ++mt)
        #pragma unroll
        for (int nt = 0; nt < 4; ++nt)
            #pragma unroll
            for (int r = 0; r < 4; ++r) acc[mt][nt][r] = 0.f;

    const int a_row = wm * 64 + (lane & 15);
    const int a_kb  = (lane >> 4) * 16;
    const int b_row = wn * 32 + ((lane >> 4) & 1) * 8 + (lane & 7);
    const int b_kb  = ((lane >> 3) & 1) * 16;

    load_chunk(0);
    cp_commit();

    if (!is_v) {
        // ---- K,Q columns: 3-product chunks ----
        for (int kt = 0; kt < NCHUNK; ++kt) {
            cp_wait0();
            __syncthreads();
            #pragma unroll
            for (int ks = 0; ks < 4; ++ks) {
                uint32_t bh[2][4], bl[2][4];
                #pragma unroll
                for (int nt2 = 0; nt2 < 2; ++nt2) {
                    uint32_t off = SWZ((uint32_t)((b_row + nt2 * 16) * 128 + ks * 32 + b_kb));
                    ldsm_x4(bh[nt2], sb + 2 * OPBYTES + off);
                    ldsm_x4(bl[nt2], sb + 3 * OPBYTES + off);
                }
                #pragma unroll
                for (int mt = 0; mt < 4; ++mt) {
                    uint32_t ah[4], al[4];
                    uint32_t off = SWZ((uint32_t)((a_row + mt * 16) * 128 + ks * 32 + a_kb));
                    ldsm_x4(ah, sb + off);
                    ldsm_x4(al, sb + OPBYTES + off);
                    #pragma unroll
                    for (int nt = 0; nt < 4; ++nt) {
                        const uint32_t* ph = &bh[nt >> 1][(nt & 1) * 2];
                        const uint32_t* pl = &bl[nt >> 1][(nt & 1) * 2];
                        mma_f16(acc[mt][nt], ah, ph);
                        mma_f16(acc[mt][nt], ah, pl);
                        mma_f16(acc[mt][nt], al, ph);
                    }
                }
            }
            __syncthreads();
            if (kt + 1 < NCHUNK) { load_chunk(kt + 1); cp_commit(); }
        }
    } else {
        // ---- V columns: single-product chunks ----
        for (int kt = 0; kt < NCHUNK; ++kt) {
            cp_wait0();
            __syncthreads();
            #pragma unroll
            for (int ks = 0; ks < 4; ++ks) {
                uint32_t bh[2][4];
                #pragma unroll
                for (int nt2 = 0; nt2 < 2; ++nt2) {
                    uint32_t off = SWZ((uint32_t)((b_row + nt2 * 16) * 128 + ks * 32 + b_kb));
                    ldsm_x4(bh[nt2], sb + 2 * OPBYTES + off);
                }
                #pragma unroll
                for (int mt = 0; mt < 4; ++mt) {
                    uint32_t ah[4];
                    uint32_t off = SWZ((uint32_t)((a_row + mt * 16) * 128 + ks * 32 + a_kb));
                    ldsm_x4(ah, sb + off);
                    #pragma unroll
                    for (int nt = 0; nt < 4; ++nt)
                        mma_f16(acc[mt][nt], ah, &bh[nt >> 1][(nt & 1) * 2]);
                }
            }
            __syncthreads();
            if (kt + 1 < NCHUNK) { load_chunk(kt + 1); cp_commit(); }
        }
    }

    // Epilogue: bias add; K,Q: split to fp16 hi/lo; V: hi only (lo never read).
    const int grp = lane >> 2, qc = (lane & 3) * 2;
    #pragma unroll
    for (int mt = 0; mt < 4; ++mt) {
        const int r0 = m0 + wm * 64 + mt * 16 + grp;
        #pragma unroll
        for (int nt = 0; nt < 4; ++nt) {
            const int col = n0 + wn * 32 + nt * 8 + qc;
            const float2 bv = *(const float2*)(bias + col);
            float o0 = acc[mt][nt][0] + bv.x, o1 = acc[mt][nt][1] + bv.y;
            float o2 = acc[mt][nt][2] + bv.x, o3 = acc[mt][nt][3] + bv.y;
            size_t off0 = (size_t)r0 * N3_ + col;
            size_t off1 = off0 + 8 * (size_t)N3_;
            if (!is_v) {
                uint32_t h2, l2;
                split2(o0, o1, h2, l2);
                *(uint32_t*)(g_kqvh + off0) = h2;
                *(uint32_t*)(g_kqvl + off0) = l2;
                split2(o2, o3, h2, l2);
                *(uint32_t*)(g_kqvh + off1) = h2;
                *(uint32_t*)(g_kqvl + off1) = l2;
            } else {
                *(uint32_t*)(g_kqvh + off0) = cvt_f16x2(o0, o1);
                *(uint32_t*)(g_kqvh + off1) = cvt_f16x2(o2, o3);
            }
        }
    }
}

// ============================================================================
// Tensor-core flash attention — fused per-key-group pipeline (R14/R15 best).
// Per key tile (64 keys), loop over 4 key-groups of 16:
//   score(24 mma) -> epilogue(8 exp, in regs) -> PV(8 mma)
// Score: 3 fp16 hi/lo products. PV: single product P_f16 x V_f16.
// K/V double-buffered: ONE __syncthreads + ONE cp.wait per key tile.
// ============================================================================
#define BQ 128
#define BK 64
#define NKT (S_ / BK)     // 32

// smem byte offsets (80.5 KB total -> 2 CTAs/SM)
#define QH_OFF 0
#define QL_OFF 16384
#define KH_OFF 32768      // + st*8192
#define KL_OFF 49152      // + st*8192
#define VH_OFF 65536      // + st*8192
#define MK_OFF 81920      // + st*256
#define ATTN_SMEM 82432

__global__ __launch_bounds__(256, 2) void attn_mma_kernel(
    const float* __restrict__ masks, float* __restrict__ out)
{
    extern __shared__ char smem[];
    const uint32_t sb = smem_u32(smem);
    const int tid = threadIdx.x, lane = tid & 31, wid = tid >> 5;
    const int b = blockIdx.z, h = blockIdx.y;
    const int q0 = blockIdx.x * BQ;
    const int grp = lane >> 2, qc = (lane & 3) * 2;

    // fragment address pieces
    const int a_row = wid * 16 + (lane & 15);                 // Q rows for this warp
    const int a_kb  = (lane >> 4) * 16;
    const int bk_sub = ((lane >> 4) & 1) * 8 + (lane & 7);    // + nt2*16 (key rows)
    const int bk_kb  = ((lane >> 3) & 1) * 16;
    const int v_row  = ((lane >> 3) & 1) * 8 + (lane & 7);    // + nt2*16
    const int v_cb   = ((lane >> 4) & 1) * 16;                // + vb*32 (d bytes)

    auto load_kv = [&](int kt2, int st2) {
        const size_t tok0 = (size_t)(b * S_) + kt2 * BK;
        #pragma unroll
        for (int i = 0; i < 2; ++i) {
            int idx = tid + i * 256;
            int r = idx >> 3, ch = idx & 7;
            uint32_t off = SWZ((uint32_t)(r * 128 + ch * 16)) + st2 * 8192;
            size_t g = (tok0 + r) * N3_ + h * HD_ + ch * 8;
            cp_async16(sb + KH_OFF + off, g_kqvh + g);
            cp_async16(sb + KL_OFF + off, g_kqvl + g);
            cp_async16(sb + VH_OFF + off, g_kqvh + g + 2 * D_);
        }
        if (tid < BK)
            cp_async4(sb + MK_OFF + (kt2 & 1) * 256 + tid * 4,
                      masks + (size_t)b * S_ + kt2 * BK + tid);
    };

    // Prologue: Q tile + K/V(0) + mask(0), one commit group.
    #pragma unroll
    for (int i = 0; i < 4; ++i) {
        int idx = tid + i * 256;
        int r = idx >> 3, ch = idx & 7;
        uint32_t off = SWZ((uint32_t)(r * 128 + ch * 16));
        size_t g = (size_t)(b * S_ + q0 + r) * N3_ + D_ + h * HD_ + ch * 8;
        cp_async16(sb + QH_OFF + off, g_kqvh + g);
        cp_async16(sb + QL_OFF + off, g_kqvl + g);
    }
    load_kv(0, 0);
    cp_commit();
    cp_wait0();
    __syncthreads();

    // Q fragments -> registers, once (loop-invariant across all key tiles).
    uint32_t aqh[4][4], aql[4][4];
    #pragma unroll
    for (int ks = 0; ks < 4; ++ks) {
        uint32_t off = SWZ((uint32_t)(a_row * 128 + ks * 32 + a_kb));
        ldsm_x4(aqh[ks], sb + QH_OFF + off);
        ldsm_x4(aql[ks], sb + QL_OFF + off);
    }

    float acc_o[8][4];
    #pragma unroll
    for (int nt = 0; nt < 8; ++nt)
        #pragma unroll
        for (int r = 0; r < 4; ++r) acc_o[nt][r] = 0.f;
    float den0 = 0.f, den1 = 0.f;

    for (int kt = 0; kt < NKT; ++kt) {
        const int st = kt & 1;
        if (kt > 0) {
            // K/V/mask(kt) arrived; all warps done reading buffer st^1.
            cp_wait0();
            __syncthreads();
        }
        // Prefetch next tile into the other buffer (overlaps this tile's math).
        if (kt + 1 < NKT) { load_kv(kt + 1, st ^ 1); cp_commit(); }

        const float* mk = (const float*)(smem + MK_OFF + st * 256);

        // ---- fused per-key-group pipeline: score -> epilogue -> PV ----
        #pragma unroll
        for (int nt2 = 0; nt2 < 4; ++nt2) {
            // score: S[16 q][16 k(nt2)] over d=64 (3 products)
            float acc_s[2][4];
            #pragma unroll
            for (int hf = 0; hf < 2; ++hf)
                #pragma unroll
                for (int r = 0; r < 4; ++r) acc_s[hf][r] = 0.f;

            #pragma unroll
            for (int ks = 0; ks < 4; ++ks) {
                uint32_t bkh[4], bkl[4];
                uint32_t off = SWZ((uint32_t)((nt2 * 16 + bk_sub) * 128 + ks * 32 + bk_kb))
                               + st * 8192;
                ldsm_x4(bkh, sb + KH_OFF + off);
                ldsm_x4(bkl, sb + KL_OFF + off);
                #pragma unroll
                for (int hf = 0; hf < 2; ++hf) {
                    float* d = acc_s[hf];
                    mma_f16(d, aqh[ks], &bkh[hf * 2]);
                    mma_f16(d, aqh[ks], &bkl[hf * 2]);
                    mma_f16(d, aql[ks], &bkh[hf * 2]);
                }
            }

            // epilogue: p = exp(clip(elu(s)))*mask_k ; pack as PV A-fragment
            uint32_t pf[4];
            #pragma unroll
            for (int hf = 0; hf < 2; ++hf) {
                const int c = nt2 * 16 + hf * 8 + qc;
                float m0 = mk[c], m1 = mk[c + 1];
                float p0 = elu_exp(acc_s[hf][0]) * m0;
                float p1 = elu_exp(acc_s[hf][1]) * m1;
                float p2 = elu_exp(acc_s[hf][2]) * m0;
                float p3 = elu_exp(acc_s[hf][3]) * m1;
                den0 += p0 + p1;
                den1 += p2 + p3;
                pf[hf * 2 + 0] = cvt_f16x2(p0, p1);
                pf[hf * 2 + 1] = cvt_f16x2(p2, p3);
            }

            // PV: O[16 q][64 d] += P[16][16(nt2)] @ V[16(nt2)][64]
            #pragma unroll
            for (int vb = 0; vb < 4; ++vb) {
                uint32_t bvh[4];
                uint32_t off = SWZ((uint32_t)((nt2 * 16 + v_row) * 128 + vb * 32 + v_cb))
                               + st * 8192;
                ldsm_x4_t(bvh, sb + VH_OFF + off);
                mma_f16(acc_o[vb * 2 + 0], pf, &bvh[0]);
                mma_f16(acc_o[vb * 2 + 1], pf, &bvh[2]);
            }
        }
        // Next iteration's cp_wait0+sync protects buffer st^1 before overwrite of st.
    }

    // ---- denominator reduce (within warp: lane bits 0,1) + writeback ----
    den0 += __shfl_xor_sync(0xffffffffu, den0, 1);
    den0 += __shfl_xor_sync(0xffffffffu, den0, 2);
    den1 += __shfl_xor_sync(0xffffffffu, den1, 1);
    den1 += __shfl_xor_sync(0xffffffffu, den1, 2);

    const int r0 = wid * 16 + grp;
    const int r1 = r0 + 8;
    float s0 = masks[(size_t)b * S_ + q0 + r0] / den0;
    float s1 = masks[(size_t)b * S_ + q0 + r1] / den1;
    #pragma unroll
    for (int nt = 0; nt < 8; ++nt) {
        const int c = nt * 8 + qc;
        float* p0 = out + (size_t)(b * S_ + q0 + r0) * D_ + h * HD_ + c;
        float* p1 = out + (size_t)(b * S_ + q0 + r1) * D_ + h * HD_ + c;
        *(float2*)p0 = make_float2(acc_o[nt][0] * s0, acc_o[nt][1] * s0);
        *(float2*)p1 = make_float2(acc_o[nt][2] * s1, acc_o[nt][3] * s1);
    }
}

// ============================================================================
// Launch
// ============================================================================
extern "C" void kernel_launch(void* const* d_in, const int* in_sizes, int n_in,
                              void* d_out, int out_size)
{
    const float *inp = nullptr, *msk = nullptr, *W = nullptr, *bias = nullptr;
    for (int i = 0; i < n_in; ++i) {
        switch (in_sizes[i]) {
            case M_ * D_:   inp  = (const float*)d_in[i]; break;  // inputs  [2,2048,1024]
            case B_ * S_:   msk  = (const float*)d_in[i]; break;  // masks   [2,2048]
            case D_ * N3_:  W    = (const float*)d_in[i]; break;  // W       [1024,3072]
            case N3_:       bias = (const float*)d_in[i]; break;  // b       [3072]
        }
    }

    cudaFuncSetAttribute(gemm_mma_kernel,
                         cudaFuncAttributeMaxDynamicSharedMemorySize, GEMM_SMEM);
    cudaFuncSetAttribute(attn_mma_kernel,
                         cudaFuncAttributeMaxDynamicSharedMemorySize, ATTN_SMEM);

    split_fused_kernel<<<SPLIT_A_BLOCKS + SPLIT_W_BLOCKS, 256>>>(inp, W);

    dim3 g1(N3_ / GN, M_ / GM);            // (24, 32)
    gemm_mma_kernel<<<g1, 256, GEMM_SMEM>>>(bias);

    dim3 g2(S_ / BQ, H_, B_);              // (16, 16, 2)
    attn_mma_kernel<<<g2, 256, ATTN_SMEM>>>(msk, (float*)d_out);
}